// round 1
// baseline (speedup 1.0000x reference)
#include <cuda_runtime.h>
#include <cuda_bf16.h>
#include <math.h>

#define N_NODES 100000
#define N_EDGES 1600000
#define TAB 4096

// -------- scratch (device globals: allocation-free) --------
__device__ float g_h[N_NODES * 64];     // node features [N,64]
__device__ float g_agg[N_NODES * 64];   // per-layer aggregation [N,64]
__device__ float g_fs[3 * N_EDGES];     // per-edge scalar filter sum, per layer
__device__ float g_tab[3][TAB + 1];     // 1-D filter lookup tables
__device__ float g_sum[64];             // column sums for the mean

__device__ __forceinline__ float softplusf(float x) {
    // max(x,0) + log(1 + exp(-|x|)) : stable, ~1e-7 abs error
    return fmaxf(x, 0.0f) + __logf(1.0f + __expf(-fabsf(x)));
}

// ---------------------------------------------------------------
// 1. Build per-layer 1-D lookup tables for the filter network.
//    g_l(s) = sum_k tanh(s*w1_k + b1_k) * (sum_j W2[k,j]) + sum(b2)
//    grid: 51 blocks (layer = b/17, 17 chunks of 256 entries)
// ---------------------------------------------------------------
__global__ void build_tables_kernel(const float* __restrict__ fW1,
                                    const float* __restrict__ fb1,
                                    const float* __restrict__ fW2,
                                    const float* __restrict__ fb2) {
    int l = blockIdx.x / 17;
    int chunk = blockIdx.x % 17;
    __shared__ float w1[64], bb1[64], w2s[64];
    __shared__ float b2s;
    int t = threadIdx.x;
    if (t < 64) {
        w1[t] = fW1[l * 64 + t];
        bb1[t] = fb1[l * 64 + t];
        float s = 0.0f;
        const float* W2 = fW2 + l * 4096;
        for (int j = 0; j < 64; j++) s += W2[t * 64 + j];
        w2s[t] = s;
    }
    if (t == 64) {
        float s = 0.0f;
        for (int k = 0; k < 64; k++) s += fb2[l * 64 + k];
        b2s = s;
    }
    __syncthreads();
    int idx = chunk * 256 + t;
    if (idx <= TAB) {
        float x = -1.0f + 2.0f * (float)idx / (float)TAB;
        float acc = b2s;
        #pragma unroll 8
        for (int k = 0; k < 64; k++)
            acc += tanhf(x * w1[k] + bb1[k]) * w2s[k];
        g_tab[l][idx] = acc;
    }
}

// ---------------------------------------------------------------
// 2. Per-edge: scaled, cutoff, and 3 table lerps -> g_fs
// ---------------------------------------------------------------
__global__ void edge_fs_kernel(const float* __restrict__ dist) {
    int e = blockIdx.x * blockDim.x + threadIdx.x;
    if (e >= N_EDGES) return;
    float d = dist[e];
    float s = d * 0.4f - 1.0f;                         // 2/CUTOFF = 0.4
    float cut = (d <= 5.0f) ? 0.5f * (__cosf(d * 0.62831853071795864769f) + 1.0f)
                            : 0.0f;                    // pi/5
    float u = (s + 1.0f) * (0.5f * (float)TAB);
    int i = (int)u;
    if (i < 0) i = 0;
    if (i > TAB - 1) i = TAB - 1;
    float fr = u - (float)i;
    #pragma unroll
    for (int l = 0; l < 3; l++) {
        float t0 = g_tab[l][i];
        float t1 = g_tab[l][i + 1];
        g_fs[l * N_EDGES + e] = cut * (t0 + fr * (t1 - t0));
    }
}

// ---------------------------------------------------------------
// 3. Embedding: h = x @ emb_W + emb_b   ([N,16] @ [16,64])
//    256 threads = 4 nodes/block
// ---------------------------------------------------------------
__global__ void embed_kernel(const float* __restrict__ x,
                             const float* __restrict__ W,
                             const float* __restrict__ b) {
    __shared__ float sW[16 * 64];
    __shared__ float sx[4][16];
    __shared__ float sb[64];
    int tid = threadIdx.x;
    for (int i = tid; i < 1024; i += 256) sW[i] = W[i];
    if (tid < 64) sb[tid] = b[tid];
    int grp = tid >> 6, j = tid & 63;
    int n = blockIdx.x * 4 + grp;                      // N%4==0 -> always valid
    if (j < 16) sx[grp][j] = x[n * 16 + j];
    __syncthreads();
    float acc = sb[j];
    #pragma unroll
    for (int k = 0; k < 16; k++) acc += sx[grp][k] * sW[k * 64 + j];
    g_h[n * 64 + j] = acc;
}

// ---------------------------------------------------------------
// 4a. Zero the aggregation buffer
// ---------------------------------------------------------------
__global__ void zero_agg_kernel() {
    int i = blockIdx.x * blockDim.x + threadIdx.x;
    if (i < N_NODES * 16)
        ((float4*)g_agg)[i] = make_float4(0.f, 0.f, 0.f, 0.f);
}

// ---------------------------------------------------------------
// 4b. Scatter: agg[row] += fs[e] * h[col]   (16 threads / edge)
//     vector atomics: red.global.add.v4.f32
// ---------------------------------------------------------------
__global__ void scatter_kernel(const int* __restrict__ ei, int l) {
    const float* __restrict__ fs = g_fs + (size_t)l * N_EDGES;
    int g = blockIdx.x * blockDim.x + threadIdx.x;
    int e = g >> 4;
    if (e >= N_EDGES) return;
    int t = g & 15;
    int r = __ldg(&ei[e]);             // row (destination)
    int c = __ldg(&ei[N_EDGES + e]);   // col (source)
    float s = __ldg(&fs[e]);
    float4 v = ((const float4*)g_h)[c * 16 + t];
    float4 m = make_float4(v.x * s, v.y * s, v.z * s, v.w * s);
    float* dst = g_agg + ((size_t)r * 16 + t) * 4;
    asm volatile("red.global.add.v4.f32 [%0], {%1, %2, %3, %4};"
                 :: "l"(dst), "f"(m.x), "f"(m.y), "f"(m.z), "f"(m.w)
                 : "memory");
}

// ---------------------------------------------------------------
// 4c. Node update:
//     out = softplus(agg@W1 + b1)@W2 + b2 ; out = out*inv*gamma+beta ; h += out
//     256 threads = 4 groups of 64; each group does 2 nodes (m, m+N/2)
//     to amortize smem weight reads.
// ---------------------------------------------------------------
__global__ void update_kernel(const float* __restrict__ W1,
                              const float* __restrict__ b1,
                              const float* __restrict__ W2,
                              const float* __restrict__ b2,
                              const float* __restrict__ gma,
                              const float* __restrict__ bta) {
    __shared__ float sW1[4096];
    __shared__ float sW2[4096];
    __shared__ float sb1[64], sb2[64], sg[64], sbt[64];
    __shared__ __align__(16) float sv[4][2][64];
    __shared__ float st[4][2][64];
    int tid = threadIdx.x;
    for (int i = tid; i < 4096; i += 256) { sW1[i] = W1[i]; sW2[i] = W2[i]; }
    if (tid < 64) { sb1[tid] = b1[tid]; sb2[tid] = b2[tid];
                    sg[tid] = gma[tid]; sbt[tid] = bta[tid]; }
    __syncthreads();
    const float inv = rsqrtf(1.0f + 1e-3f);
    const int HALF = N_NODES / 2;                      // 50000, %4==0
    int j = tid & 63, grp = tid >> 6;

    for (int mb = blockIdx.x * 4; mb < HALF; mb += gridDim.x * 4) {
        int na = mb + grp;
        int nb = na + HALF;
        sv[grp][0][j] = g_agg[na * 64 + j];
        sv[grp][1][j] = g_agg[nb * 64 + j];
        __syncthreads();

        float a0 = sb1[j], a1 = sb1[j];
        #pragma unroll
        for (int k = 0; k < 64; k += 4) {
            float4 va = *(const float4*)&sv[grp][0][k];
            float4 vb = *(const float4*)&sv[grp][1][k];
            float w0 = sW1[(k + 0) * 64 + j];
            float w1 = sW1[(k + 1) * 64 + j];
            float w2 = sW1[(k + 2) * 64 + j];
            float w3 = sW1[(k + 3) * 64 + j];
            a0 = fmaf(va.x, w0, a0); a1 = fmaf(vb.x, w0, a1);
            a0 = fmaf(va.y, w1, a0); a1 = fmaf(vb.y, w1, a1);
            a0 = fmaf(va.z, w2, a0); a1 = fmaf(vb.z, w2, a1);
            a0 = fmaf(va.w, w3, a0); a1 = fmaf(vb.w, w3, a1);
        }
        st[grp][0][j] = softplusf(a0);
        st[grp][1][j] = softplusf(a1);
        __syncthreads();

        float c0 = sb2[j], c1 = sb2[j];
        #pragma unroll
        for (int k = 0; k < 64; k += 4) {
            float4 ta = *(const float4*)&st[grp][0][k];
            float4 tb = *(const float4*)&st[grp][1][k];
            float w0 = sW2[(k + 0) * 64 + j];
            float w1 = sW2[(k + 1) * 64 + j];
            float w2 = sW2[(k + 2) * 64 + j];
            float w3 = sW2[(k + 3) * 64 + j];
            c0 = fmaf(ta.x, w0, c0); c1 = fmaf(tb.x, w0, c1);
            c0 = fmaf(ta.y, w1, c0); c1 = fmaf(tb.y, w1, c1);
            c0 = fmaf(ta.z, w2, c0); c1 = fmaf(tb.z, w2, c1);
            c0 = fmaf(ta.w, w3, c0); c1 = fmaf(tb.w, w3, c1);
        }
        float o0 = c0 * inv * sg[j] + sbt[j];
        float o1 = c1 * inv * sg[j] + sbt[j];
        g_h[na * 64 + j] += o0;
        g_h[nb * 64 + j] += o1;
    }
}

// ---------------------------------------------------------------
// 5. Mean over nodes (column sums into g_sum)
// ---------------------------------------------------------------
__global__ void zero_sum_kernel() {
    if (threadIdx.x < 64) g_sum[threadIdx.x] = 0.0f;
}

__global__ void mean_kernel() {
    int j = threadIdx.x & 63;
    int grp = threadIdx.x >> 6;
    float acc = 0.0f;
    for (int n = blockIdx.x * 4 + grp; n < N_NODES; n += gridDim.x * 4)
        acc += g_h[n * 64 + j];
    __shared__ float s[256];
    s[threadIdx.x] = acc;
    __syncthreads();
    if (threadIdx.x < 64)
        atomicAdd(&g_sum[j], s[j] + s[64 + j] + s[128 + j] + s[192 + j]);
}

// ---------------------------------------------------------------
// 6. Output MLP (single block)
// ---------------------------------------------------------------
__global__ void final_kernel(const float* __restrict__ oW1, const float* __restrict__ ob1,
                             const float* __restrict__ og1, const float* __restrict__ obt1,
                             const float* __restrict__ oW2, const float* __restrict__ ob2,
                             const float* __restrict__ og2, const float* __restrict__ obt2,
                             const float* __restrict__ fin_W, const float* __restrict__ fin_b,
                             float* __restrict__ out) {
    __shared__ float g[64], a1[32], a2[32];
    const float inv = rsqrtf(1.0f + 1e-3f);
    int t = threadIdx.x;  // 64 threads
    if (t < 64) g[t] = g_sum[t] * (1.0f / (float)N_NODES);
    __syncthreads();
    if (t < 32) {
        float acc = ob1[t];
        for (int k = 0; k < 64; k++) acc += g[k] * oW1[k * 32 + t];
        a1[t] = softplusf(acc) * inv * og1[t] + obt1[t];
    }
    __syncthreads();
    if (t < 32) {
        float acc = ob2[t];
        for (int k = 0; k < 32; k++) acc += a1[k] * oW2[k * 32 + t];
        a2[t] = softplusf(acc) * inv * og2[t] + obt2[t];
    }
    __syncthreads();
    if (t < 3) {
        float acc = fin_b[t];
        for (int k = 0; k < 32; k++) acc += a2[k] * fin_W[k * 3 + t];
        out[t] = acc;
    }
}

// ---------------------------------------------------------------
extern "C" void kernel_launch(void* const* d_in, const int* in_sizes, int n_in,
                              void* d_out, int out_size) {
    const float* x      = (const float*)d_in[0];
    const int*   ei     = (const int*)  d_in[1];
    const float* dist   = (const float*)d_in[2];
    // d_in[3] = edge_attr (unused by the reference math)
    const float* emb_W  = (const float*)d_in[4];
    const float* emb_b  = (const float*)d_in[5];
    const float* fW1    = (const float*)d_in[6];
    const float* fb1    = (const float*)d_in[7];
    const float* fW2    = (const float*)d_in[8];
    const float* fb2    = (const float*)d_in[9];
    const float* iW1    = (const float*)d_in[10];
    const float* ib1    = (const float*)d_in[11];
    const float* iW2    = (const float*)d_in[12];
    const float* ib2    = (const float*)d_in[13];
    const float* gma    = (const float*)d_in[14];
    const float* bta    = (const float*)d_in[15];
    const float* oW1    = (const float*)d_in[16];
    const float* ob1    = (const float*)d_in[17];
    const float* og1    = (const float*)d_in[18];
    const float* obt1   = (const float*)d_in[19];
    const float* oW2    = (const float*)d_in[20];
    const float* ob2    = (const float*)d_in[21];
    const float* og2    = (const float*)d_in[22];
    const float* obt2   = (const float*)d_in[23];
    const float* fin_W  = (const float*)d_in[24];
    const float* fin_b  = (const float*)d_in[25];
    float* out = (float*)d_out;

    build_tables_kernel<<<51, 256>>>(fW1, fb1, fW2, fb2);
    edge_fs_kernel<<<(N_EDGES + 255) / 256, 256>>>(dist);
    embed_kernel<<<N_NODES / 4, 256>>>(x, emb_W, emb_b);

    for (int l = 0; l < 3; l++) {
        zero_agg_kernel<<<(N_NODES * 16 + 255) / 256, 256>>>();
        scatter_kernel<<<(N_EDGES * 16 + 255) / 256, 256>>>(ei, l);
        update_kernel<<<2048, 256>>>(iW1 + l * 4096, ib1 + l * 64,
                                     iW2 + l * 4096, ib2 + l * 64,
                                     gma + l * 64, bta + l * 64);
    }

    zero_sum_kernel<<<1, 64>>>();
    mean_kernel<<<512, 256>>>();
    final_kernel<<<1, 64>>>(oW1, ob1, og1, obt1, oW2, ob2, og2, obt2,
                            fin_W, fin_b, out);
}

// round 2
// speedup vs baseline: 1.7412x; 1.7412x over previous
#include <cuda_runtime.h>
#include <cuda_bf16.h>
#include <math.h>

#define NN 100000
#define NE 1600000
#define TAB 4096
#define NSCAN 98          // ceil((NN+1)/1024)

// -------- scratch (device globals: allocation-free) --------
__device__ float g_h[NN * 64];      // node features
__device__ float g_agg[NN * 64];    // per-layer aggregation
__device__ float g_tab[3][TAB + 1]; // 1-D filter lookup tables
__device__ float g_sum[64];         // column sums for the mean
__device__ int   g_deg[NN];
__device__ int   g_off[NN + 1];
__device__ int   g_cursor[NN];
__device__ int   g_bsum[NSCAN];
__device__ int   g_bofs[NSCAN];
__device__ int   g_ecol[NE];        // CSR: source node per edge slot
__device__ float g_efs[3 * NE];     // CSR-permuted fs, per layer

__device__ __forceinline__ float softplusf(float x) {
    return fmaxf(x, 0.0f) + __logf(1.0f + __expf(-fabsf(x)));
}

__device__ __forceinline__ unsigned f2tf(float x) {
    unsigned r;
    asm("cvt.rna.tf32.f32 %0, %1;" : "=r"(r) : "f"(x));
    return r;
}

// ---------------------------------------------------------------
// 1. Per-layer 1-D filter lookup tables.
// ---------------------------------------------------------------
__global__ void build_tables_kernel(const float* __restrict__ fW1,
                                    const float* __restrict__ fb1,
                                    const float* __restrict__ fW2,
                                    const float* __restrict__ fb2) {
    int l = blockIdx.x / 17;
    int chunk = blockIdx.x % 17;
    __shared__ float w1[64], bb1[64], w2s[64];
    __shared__ float b2s;
    int t = threadIdx.x;
    if (t < 64) {
        w1[t] = fW1[l * 64 + t];
        bb1[t] = fb1[l * 64 + t];
        float s = 0.0f;
        const float* W2 = fW2 + l * 4096;
        for (int j = 0; j < 64; j++) s += W2[t * 64 + j];
        w2s[t] = s;
    }
    if (t == 64) {
        float s = 0.0f;
        for (int k = 0; k < 64; k++) s += fb2[l * 64 + k];
        b2s = s;
    }
    __syncthreads();
    int idx = chunk * 256 + t;
    if (idx <= TAB) {
        float x = -1.0f + 2.0f * (float)idx / (float)TAB;
        float acc = b2s;
        #pragma unroll 8
        for (int k = 0; k < 64; k++)
            acc += tanhf(x * w1[k] + bb1[k]) * w2s[k];
        g_tab[l][idx] = acc;
    }
}

// ---------------------------------------------------------------
// 2. CSR construction
// ---------------------------------------------------------------
__global__ void zero_deg_kernel() {
    int i = blockIdx.x * blockDim.x + threadIdx.x;
    if (i < NN) g_deg[i] = 0;
}

__global__ void count_kernel(const int* __restrict__ ei) {
    int e = blockIdx.x * blockDim.x + threadIdx.x;
    if (e < NE) atomicAdd(&g_deg[ei[e]], 1);
}

__global__ void scan1_kernel() {
    int tid = threadIdx.x, b = blockIdx.x;
    int i = b * 1024 + tid;
    int v = (i < NN) ? g_deg[i] : 0;
    int x = v;
    #pragma unroll
    for (int d = 1; d < 32; d <<= 1) {
        int y = __shfl_up_sync(0xffffffffu, x, d);
        if ((tid & 31) >= d) x += y;
    }
    __shared__ int ws[32];
    if ((tid & 31) == 31) ws[tid >> 5] = x;
    __syncthreads();
    if (tid < 32) {
        int y = ws[tid];
        #pragma unroll
        for (int d = 1; d < 32; d <<= 1) {
            int z = __shfl_up_sync(0xffffffffu, y, d);
            if (tid >= d) y += z;
        }
        ws[tid] = y;
    }
    __syncthreads();
    int warp = tid >> 5;
    int base = (warp > 0) ? ws[warp - 1] : 0;
    int excl = base + x - v;
    if (i <= NN) g_off[i] = excl;
    if (tid == 0) g_bsum[b] = ws[31];
}

__global__ void scan2_kernel() {
    if (threadIdx.x == 0) {
        int s = 0;
        for (int b = 0; b < NSCAN; b++) { g_bofs[b] = s; s += g_bsum[b]; }
    }
}

__global__ void scan3_kernel() {
    int tid = threadIdx.x, b = blockIdx.x;
    int i = b * 1024 + tid;
    if (i <= NN) {
        int o = g_off[i] + g_bofs[b];
        g_off[i] = o;
        if (i < NN) g_cursor[i] = o;
    }
}

// fill CSR slots; fused per-edge filter evaluation (3 table lerps)
__global__ void fill_kernel(const int* __restrict__ ei,
                            const float* __restrict__ dist) {
    int e = blockIdx.x * blockDim.x + threadIdx.x;
    if (e >= NE) return;
    int r = __ldg(&ei[e]);
    int c = __ldg(&ei[NE + e]);
    float d = __ldg(&dist[e]);
    float cut = (d <= 5.0f) ? 0.5f * (__cosf(d * 0.62831853071795864769f) + 1.0f)
                            : 0.0f;
    float u = d * (0.2f * (float)TAB);   // maps [0,5] -> [0,TAB]
    int i = (int)u;
    if (i < 0) i = 0;
    if (i > TAB - 1) i = TAB - 1;
    float fr = u - (float)i;
    int pos = atomicAdd(&g_cursor[r], 1);
    g_ecol[pos] = c;
    #pragma unroll
    for (int l = 0; l < 3; l++) {
        float t0 = g_tab[l][i];
        float t1 = g_tab[l][i + 1];
        g_efs[l * NE + pos] = cut * (t0 + fr * (t1 - t0));
    }
}

// ---------------------------------------------------------------
// 3. Embedding: h = x @ emb_W + emb_b
// ---------------------------------------------------------------
__global__ void embed_kernel(const float* __restrict__ x,
                             const float* __restrict__ W,
                             const float* __restrict__ b) {
    __shared__ float sW[16 * 64];
    __shared__ float sx[4][16];
    __shared__ float sb[64];
    int tid = threadIdx.x;
    for (int i = tid; i < 1024; i += 256) sW[i] = W[i];
    if (tid < 64) sb[tid] = b[tid];
    int grp = tid >> 6, j = tid & 63;
    int n = blockIdx.x * 4 + grp;
    if (j < 16) sx[grp][j] = x[n * 16 + j];
    __syncthreads();
    float acc = sb[j];
    #pragma unroll
    for (int k = 0; k < 16; k++) acc += sx[grp][k] * sW[k * 64 + j];
    g_h[n * 64 + j] = acc;
}

// ---------------------------------------------------------------
// 4a. Gather-aggregate: agg[n] = sum_{e in csr(n)} fs[e] * h[col[e]]
//     16 threads per node, float4 per thread, no atomics.
// ---------------------------------------------------------------
__global__ void gather_kernel(int l) {
    const float* __restrict__ fs = g_efs + (size_t)l * NE;
    int node = blockIdx.x * 16 + (threadIdx.x >> 4);
    if (node >= NN) return;
    int t = threadIdx.x & 15;
    int j = g_off[node];
    int jend = g_off[node + 1];
    float4 acc = make_float4(0.f, 0.f, 0.f, 0.f);
    // unroll by 2 for memory-level parallelism
    for (; j + 2 <= jend; j += 2) {
        int c0 = __ldg(&g_ecol[j]);
        int c1 = __ldg(&g_ecol[j + 1]);
        float f0 = __ldg(&fs[j]);
        float f1 = __ldg(&fs[j + 1]);
        float4 v0 = __ldg(&((const float4*)g_h)[c0 * 16 + t]);
        float4 v1 = __ldg(&((const float4*)g_h)[c1 * 16 + t]);
        acc.x = fmaf(f0, v0.x, acc.x); acc.y = fmaf(f0, v0.y, acc.y);
        acc.z = fmaf(f0, v0.z, acc.z); acc.w = fmaf(f0, v0.w, acc.w);
        acc.x = fmaf(f1, v1.x, acc.x); acc.y = fmaf(f1, v1.y, acc.y);
        acc.z = fmaf(f1, v1.z, acc.z); acc.w = fmaf(f1, v1.w, acc.w);
    }
    if (j < jend) {
        int c0 = __ldg(&g_ecol[j]);
        float f0 = __ldg(&fs[j]);
        float4 v0 = __ldg(&((const float4*)g_h)[c0 * 16 + t]);
        acc.x = fmaf(f0, v0.x, acc.x); acc.y = fmaf(f0, v0.y, acc.y);
        acc.z = fmaf(f0, v0.z, acc.z); acc.w = fmaf(f0, v0.w, acc.w);
    }
    ((float4*)g_agg)[node * 16 + t] = acc;
}

// ---------------------------------------------------------------
// 4b. Node update via tf32 mma.sync:
//     out = softplus(agg@W1+b1)@W2+b2 ; out = out*inv*gamma+beta ; h += out
//     128 nodes/block, 8 warps, each warp: 16 rows x 64 cols.
//     W split hi/lo in tf32 (2 mmas) to kill systematic rounding bias.
// ---------------------------------------------------------------
#define SMEM_UPD 101376
// layout: sA[128*68] f32 @0 (34816B), sW1p float4[64*32] @34816,
//         sW2p float4[64*32] @67584, sb1 @100352, sb2 @100608,
//         sgm @100864, sbt @101120

__device__ __forceinline__ void mma8(float c[4], unsigned a0, unsigned a1,
                                     unsigned a2, unsigned a3,
                                     unsigned b0, unsigned b1) {
    asm volatile(
        "mma.sync.aligned.m16n8k8.row.col.f32.tf32.tf32.f32 "
        "{%0,%1,%2,%3}, {%4,%5,%6,%7}, {%8,%9}, {%0,%1,%2,%3};"
        : "+f"(c[0]), "+f"(c[1]), "+f"(c[2]), "+f"(c[3])
        : "r"(a0), "r"(a1), "r"(a2), "r"(a3), "r"(b0), "r"(b1));
}

__global__ __launch_bounds__(256) void update_mma_kernel(
        const float* __restrict__ W1, const float* __restrict__ b1,
        const float* __restrict__ W2, const float* __restrict__ b2,
        const float* __restrict__ gma, const float* __restrict__ bta) {
    extern __shared__ char smem_raw[];
    float*  sA   = (float*)smem_raw;
    float4* sW1p = (float4*)(smem_raw + 34816);
    float4* sW2p = (float4*)(smem_raw + 67584);
    float*  sb1  = (float*)(smem_raw + 100352);
    float*  sb2  = (float*)(smem_raw + 100608);
    float*  sgm  = (float*)(smem_raw + 100864);
    float*  sbt  = (float*)(smem_raw + 101120);

    const float inv = rsqrtf(1.0f + 1e-3f);
    int tid = threadIdx.x;
    int rowbase = blockIdx.x * 128;

    if (tid < 64) {
        sb1[tid] = b1[tid];
        sb2[tid] = b2[tid];
        sgm[tid] = gma[tid] * inv;
        sbt[tid] = bta[tid];
    }

    // pack W1/W2 into per-lane mma B fragments: {hi0,hi1,lo0,lo1}
    for (int i = tid; i < 2048; i += 256) {
        int k8 = i >> 8;
        int nt = (i >> 5) & 7;
        int ln = i & 31;
        int q = ln & 3, g = ln >> 2;
        int r0 = k8 * 8 + q, r1 = r0 + 4, cn = nt * 8 + g;
        {
            float w0 = W1[r0 * 64 + cn], w1 = W1[r1 * 64 + cn];
            unsigned h0 = f2tf(w0), h1 = f2tf(w1);
            unsigned l0 = f2tf(w0 - __uint_as_float(h0));
            unsigned l1 = f2tf(w1 - __uint_as_float(h1));
            sW1p[i] = make_float4(__uint_as_float(h0), __uint_as_float(h1),
                                  __uint_as_float(l0), __uint_as_float(l1));
        }
        {
            float w0 = W2[r0 * 64 + cn], w1 = W2[r1 * 64 + cn];
            unsigned h0 = f2tf(w0), h1 = f2tf(w1);
            unsigned l0 = f2tf(w0 - __uint_as_float(h0));
            unsigned l1 = f2tf(w1 - __uint_as_float(h1));
            sW2p[i] = make_float4(__uint_as_float(h0), __uint_as_float(h1),
                                  __uint_as_float(l0), __uint_as_float(l1));
        }
    }

    // load A tile (tf32-rounded), zero-pad OOB rows
    for (int i = tid; i < 2048; i += 256) {
        int r = i >> 4, c4 = i & 15;
        float4 v = make_float4(0.f, 0.f, 0.f, 0.f);
        if (rowbase + r < NN) v = ((const float4*)g_agg)[(rowbase + r) * 16 + c4];
        float4 o;
        o.x = __uint_as_float(f2tf(v.x));
        o.y = __uint_as_float(f2tf(v.y));
        o.z = __uint_as_float(f2tf(v.z));
        o.w = __uint_as_float(f2tf(v.w));
        *(float4*)&sA[r * 68 + c4 * 4] = o;
    }
    __syncthreads();

    int warp = tid >> 5, lane = tid & 31;
    int r0 = warp * 16 + (lane >> 2);   // local row (and r0+8)
    int tig = lane & 3;

    float c[8][4];
    // ---- GEMM1: C = A @ W1 + b1 ----
    #pragma unroll
    for (int nt = 0; nt < 8; nt++) {
        int col0 = nt * 8 + tig * 2;
        c[nt][0] = c[nt][2] = sb1[col0];
        c[nt][1] = c[nt][3] = sb1[col0 + 1];
    }
    #pragma unroll
    for (int k8 = 0; k8 < 8; k8++) {
        int kc = k8 * 8 + tig;
        unsigned a0 = __float_as_uint(sA[r0 * 68 + kc]);
        unsigned a1 = __float_as_uint(sA[(r0 + 8) * 68 + kc]);
        unsigned a2 = __float_as_uint(sA[r0 * 68 + kc + 4]);
        unsigned a3 = __float_as_uint(sA[(r0 + 8) * 68 + kc + 4]);
        #pragma unroll
        for (int nt = 0; nt < 8; nt++) {
            float4 w = sW1p[(k8 * 8 + nt) * 32 + lane];
            mma8(c[nt], a0, a1, a2, a3, __float_as_uint(w.x), __float_as_uint(w.y));
            mma8(c[nt], a0, a1, a2, a3, __float_as_uint(w.z), __float_as_uint(w.w));
        }
    }
    // epilogue1: softplus -> write back to sA (tf32), own rows only
    __syncwarp();
    #pragma unroll
    for (int nt = 0; nt < 8; nt++) {
        int col0 = nt * 8 + tig * 2;
        float2 t0, t1;
        t0.x = __uint_as_float(f2tf(softplusf(c[nt][0])));
        t0.y = __uint_as_float(f2tf(softplusf(c[nt][1])));
        t1.x = __uint_as_float(f2tf(softplusf(c[nt][2])));
        t1.y = __uint_as_float(f2tf(softplusf(c[nt][3])));
        *(float2*)&sA[r0 * 68 + col0] = t0;
        *(float2*)&sA[(r0 + 8) * 68 + col0] = t1;
    }
    __syncwarp();

    // ---- GEMM2: C = T @ W2 + b2 ----
    #pragma unroll
    for (int nt = 0; nt < 8; nt++) {
        int col0 = nt * 8 + tig * 2;
        c[nt][0] = c[nt][2] = sb2[col0];
        c[nt][1] = c[nt][3] = sb2[col0 + 1];
    }
    #pragma unroll
    for (int k8 = 0; k8 < 8; k8++) {
        int kc = k8 * 8 + tig;
        unsigned a0 = __float_as_uint(sA[r0 * 68 + kc]);
        unsigned a1 = __float_as_uint(sA[(r0 + 8) * 68 + kc]);
        unsigned a2 = __float_as_uint(sA[r0 * 68 + kc + 4]);
        unsigned a3 = __float_as_uint(sA[(r0 + 8) * 68 + kc + 4]);
        #pragma unroll
        for (int nt = 0; nt < 8; nt++) {
            float4 w = sW2p[(k8 * 8 + nt) * 32 + lane];
            mma8(c[nt], a0, a1, a2, a3, __float_as_uint(w.x), __float_as_uint(w.y));
            mma8(c[nt], a0, a1, a2, a3, __float_as_uint(w.z), __float_as_uint(w.w));
        }
    }
    // epilogue2: BN + residual add into h
    int ga = rowbase + r0;
    int gb = ga + 8;
    #pragma unroll
    for (int nt = 0; nt < 8; nt++) {
        int col0 = nt * 8 + tig * 2;
        float m0 = sgm[col0], m1 = sgm[col0 + 1];
        float t0 = sbt[col0], t1 = sbt[col0 + 1];
        if (ga < NN) {
            float2* p = (float2*)&g_h[ga * 64 + col0];
            float2 v = *p;
            v.x += c[nt][0] * m0 + t0;
            v.y += c[nt][1] * m1 + t1;
            *p = v;
        }
        if (gb < NN) {
            float2* p = (float2*)&g_h[gb * 64 + col0];
            float2 v = *p;
            v.x += c[nt][2] * m0 + t0;
            v.y += c[nt][3] * m1 + t1;
            *p = v;
        }
    }
}

// ---------------------------------------------------------------
// 5. Mean over nodes
// ---------------------------------------------------------------
__global__ void zero_sum_kernel() {
    if (threadIdx.x < 64) g_sum[threadIdx.x] = 0.0f;
}

__global__ void mean_kernel() {
    int j = threadIdx.x & 63;
    int grp = threadIdx.x >> 6;
    float acc = 0.0f;
    for (int n = blockIdx.x * 4 + grp; n < NN; n += gridDim.x * 4)
        acc += g_h[n * 64 + j];
    __shared__ float s[256];
    s[threadIdx.x] = acc;
    __syncthreads();
    if (threadIdx.x < 64)
        atomicAdd(&g_sum[j], s[j] + s[64 + j] + s[128 + j] + s[192 + j]);
}

// ---------------------------------------------------------------
// 6. Output MLP (single block)
// ---------------------------------------------------------------
__global__ void final_kernel(const float* __restrict__ oW1, const float* __restrict__ ob1,
                             const float* __restrict__ og1, const float* __restrict__ obt1,
                             const float* __restrict__ oW2, const float* __restrict__ ob2,
                             const float* __restrict__ og2, const float* __restrict__ obt2,
                             const float* __restrict__ fin_W, const float* __restrict__ fin_b,
                             float* __restrict__ out) {
    __shared__ float g[64], a1[32], a2[32];
    const float inv = rsqrtf(1.0f + 1e-3f);
    int t = threadIdx.x;
    if (t < 64) g[t] = g_sum[t] * (1.0f / (float)NN);
    __syncthreads();
    if (t < 32) {
        float acc = ob1[t];
        for (int k = 0; k < 64; k++) acc += g[k] * oW1[k * 32 + t];
        a1[t] = softplusf(acc) * inv * og1[t] + obt1[t];
    }
    __syncthreads();
    if (t < 32) {
        float acc = ob2[t];
        for (int k = 0; k < 32; k++) acc += a1[k] * oW2[k * 32 + t];
        a2[t] = softplusf(acc) * inv * og2[t] + obt2[t];
    }
    __syncthreads();
    if (t < 3) {
        float acc = fin_b[t];
        for (int k = 0; k < 32; k++) acc += a2[k] * fin_W[k * 3 + t];
        out[t] = acc;
    }
}

// ---------------------------------------------------------------
extern "C" void kernel_launch(void* const* d_in, const int* in_sizes, int n_in,
                              void* d_out, int out_size) {
    const float* x      = (const float*)d_in[0];
    const int*   ei     = (const int*)  d_in[1];
    const float* dist   = (const float*)d_in[2];
    const float* emb_W  = (const float*)d_in[4];
    const float* emb_b  = (const float*)d_in[5];
    const float* fW1    = (const float*)d_in[6];
    const float* fb1    = (const float*)d_in[7];
    const float* fW2    = (const float*)d_in[8];
    const float* fb2    = (const float*)d_in[9];
    const float* iW1    = (const float*)d_in[10];
    const float* ib1    = (const float*)d_in[11];
    const float* iW2    = (const float*)d_in[12];
    const float* ib2    = (const float*)d_in[13];
    const float* gma    = (const float*)d_in[14];
    const float* bta    = (const float*)d_in[15];
    const float* oW1    = (const float*)d_in[16];
    const float* ob1    = (const float*)d_in[17];
    const float* og1    = (const float*)d_in[18];
    const float* obt1   = (const float*)d_in[19];
    const float* oW2    = (const float*)d_in[20];
    const float* ob2    = (const float*)d_in[21];
    const float* og2    = (const float*)d_in[22];
    const float* obt2   = (const float*)d_in[23];
    const float* fin_W  = (const float*)d_in[24];
    const float* fin_b  = (const float*)d_in[25];
    float* out = (float*)d_out;

    static int smem_set = 0;
    if (!smem_set) {
        cudaFuncSetAttribute(update_mma_kernel,
                             cudaFuncAttributeMaxDynamicSharedMemorySize,
                             SMEM_UPD);
        smem_set = 1;
    }

    build_tables_kernel<<<51, 256>>>(fW1, fb1, fW2, fb2);

    // CSR construction
    zero_deg_kernel<<<(NN + 255) / 256, 256>>>();
    count_kernel<<<(NE + 255) / 256, 256>>>(ei);
    scan1_kernel<<<NSCAN, 1024>>>();
    scan2_kernel<<<1, 32>>>();
    scan3_kernel<<<NSCAN, 1024>>>();
    fill_kernel<<<(NE + 255) / 256, 256>>>(ei, dist);

    embed_kernel<<<NN / 4, 256>>>(x, emb_W, emb_b);

    for (int l = 0; l < 3; l++) {
        gather_kernel<<<(NN + 15) / 16, 256>>>(l);
        update_mma_kernel<<<(NN + 127) / 128, 256, SMEM_UPD>>>(
            iW1 + l * 4096, ib1 + l * 64,
            iW2 + l * 4096, ib2 + l * 64,
            gma + l * 64, bta + l * 64);
    }

    zero_sum_kernel<<<1, 64>>>();
    mean_kernel<<<512, 256>>>();
    final_kernel<<<1, 64>>>(oW1, ob1, og1, obt1, oW2, ob2, og2, obt2,
                            fin_W, fin_b, out);
}